// round 16
// baseline (speedup 1.0000x reference)
#include <cuda_runtime.h>

// ResamplerLayer: trilinear resample of [B,D,H,W,C=4] fp32 volume at
// [B,OD,OH,OW,3] continuous coords (ZERO boundary: weights from CLAMPED
// corner indices). Output [B,OD,OH,OW,4] fp32.
//
// R4:  2 lanes per point (lane bit = floor-W / ceil-W) -> adjacent 16B pair
//      coalesces into one L1tex wavefront per gather instruction.
// R6:  2 points per thread (batch 0 + batch 1, same spatial offset) -> MLP=8.
// R8:  L2 eviction policies: volume=evict_last (pin 67MB in 126MB L2),
//      coords=evict_first, stores=st.global.cs.
// R9:  __launch_bounds__(256,7), 32 regs.
// R15: PERSISTENT grid. 6912 CTAs at occ 7 = 6.67 waves -> 5.67 wave
//      transitions (~2360 cyc each) + partial tail wave + per-wave CTA
//      spread. Launch exactly 148*7=1036 CTAs with a grid-stride loop
//      (warp-granular stride: NPTS % 32 == 0, stride % 32 == 0, so the
//      lane-pair shuffles stay uniform within every active warp).

#define Bk   2
#define Dk   128
#define Hk   128
#define Wk   128
#define ODk  96
#define OHk  96
#define OWk  96

#define NPTS (Bk * ODk * OHk * OWk)          // 1,769,472
#define PTS_PER_BATCH (ODk * OHk * OWk)      // 884,736 == NPTS/2
#define VOLSZ (Dk * Hk * Wk)

#define NSM        148
#define CTAS_PER_SM 7
#define PERSIST_CTAS (NSM * CTAS_PER_SM)     // 1036
#define CTA_THREADS 256

__device__ __forceinline__ unsigned long long pol_evict_last() {
    unsigned long long p;
    asm("createpolicy.fractional.L2::evict_last.b64 %0, 1.0;" : "=l"(p));
    return p;
}

__device__ __forceinline__ unsigned long long pol_evict_first() {
    unsigned long long p;
    asm("createpolicy.fractional.L2::evict_first.b64 %0, 1.0;" : "=l"(p));
    return p;
}

// Volume gather: non-coherent load, pinned in L2 (evict_last policy).
__device__ __forceinline__ float4 ldg_vol(const float4* p, unsigned long long pol) {
    float4 v;
    asm volatile("ld.global.nc.L2::cache_hint.v4.f32 {%0,%1,%2,%3}, [%4], %5;"
                 : "=f"(v.x), "=f"(v.y), "=f"(v.z), "=f"(v.w)
                 : "l"(p), "l"(pol));
    return v;
}

// Coord load: streaming (evict_first policy).
__device__ __forceinline__ float ldg_coord(const float* p, unsigned long long pol) {
    float v;
    asm volatile("ld.global.nc.L2::cache_hint.f32 %0, [%1], %2;"
                 : "=f"(v) : "l"(p), "l"(pol));
    return v;
}

// Output store: cache-streaming.
__device__ __forceinline__ void stg_out(float4* p, float4 v) {
    asm volatile("st.global.cs.v4.f32 [%0], {%1,%2,%3,%4};"
                 :: "l"(p), "f"(v.x), "f"(v.y), "f"(v.z), "f"(v.w) : "memory");
}

__device__ __forceinline__ float4 f4_fma2(float4 a, float wa, float4 b, float wb) {
    float4 r;
    r.x = fmaf(a.x, wa, b.x * wb);
    r.y = fmaf(a.y, wa, b.y * wb);
    r.z = fmaf(a.z, wa, b.z * wb);
    r.w = fmaf(a.w, wa, b.w * wb);
    return r;
}

struct PtAddr {
    const float4* q;   // volume base + batch + this lane's W
    int rFF, rCF, rFC, rCC;
    float w0d, w1d, w0h, w1h, w0w, w1w;
};

__device__ __forceinline__ PtAddr make_addr(const float4* __restrict__ vol,
                                            const float* __restrict__ coords,
                                            int p, int batch_base, int s,
                                            unsigned long long polF) {
    const float* cp = coords + (size_t)p * 3;
    float cd = ldg_coord(cp + 0, polF);
    float ch = ldg_coord(cp + 1, polF);
    float cw = ldg_coord(cp + 2, polF);

    int fd0 = (int)floorf(cd);
    int fh0 = (int)floorf(ch);
    int fw0 = (int)floorf(cw);

    int fd  = min(max(fd0,     0), Dk - 1);
    int fh  = min(max(fh0,     0), Hk - 1);
    int fw  = min(max(fw0,     0), Wk - 1);
    int cdI = min(max(fd0 + 1, 0), Dk - 1);
    int chI = min(max(fh0 + 1, 0), Hk - 1);
    int cwI = min(max(fw0 + 1, 0), Wk - 1);

    PtAddr a;
    a.w0d = cd - (float)fd;    a.w1d = (float)cdI - cd;
    a.w0h = ch - (float)fh;    a.w1h = (float)chI - ch;
    a.w0w = cw - (float)fw;    a.w1w = (float)cwI - cw;

    int wsel = s ? cwI : fw;
    a.q = vol + batch_base + wsel;
    a.rFF = (fd  * Hk + fh ) * Wk;
    a.rCF = (cdI * Hk + fh ) * Wk;
    a.rFC = (fd  * Hk + chI) * Wk;
    a.rCC = (cdI * Hk + chI) * Wk;
    return a;
}

__global__ __launch_bounds__(CTA_THREADS, CTAS_PER_SM)
void resampler_kernel(const float4* __restrict__ vol,     // [B,D,H,W] of float4
                      const float*  __restrict__ coords,  // [NPTS,3]
                      float4*       __restrict__ out)     // [NPTS] of float4
{
    unsigned long long polL = pol_evict_last();
    unsigned long long polF = pol_evict_first();

    const int stride = PERSIST_CTAS * CTA_THREADS;        // % 32 == 0

    for (int t = blockIdx.x * CTA_THREADS + threadIdx.x; t < NPTS; t += stride) {
        int q = t >> 1;                                   // pair index
        int s = t & 1;                                    // 0 = floor-W, 1 = ceil-W

        int p0 = q;                    // batch 0
        int p1 = q + PTS_PER_BATCH;    // batch 1 (same spatial offset)

        PtAddr a0 = make_addr(vol, coords, p0, 0,     s, polF);
        PtAddr a1 = make_addr(vol, coords, p1, VOLSZ, s, polF);

        // 8 gathers back-to-back: MLP=8 per lane; lane pairs share 128B lines.
        float4 s0FF = ldg_vol(a0.q + a0.rFF, polL);
        float4 s0CF = ldg_vol(a0.q + a0.rCF, polL);
        float4 s0FC = ldg_vol(a0.q + a0.rFC, polL);
        float4 s0CC = ldg_vol(a0.q + a0.rCC, polL);
        float4 s1FF = ldg_vol(a1.q + a1.rFF, polL);
        float4 s1CF = ldg_vol(a1.q + a1.rCF, polL);
        float4 s1FC = ldg_vol(a1.q + a1.rFC, polL);
        float4 s1CC = ldg_vol(a1.q + a1.rCC, polL);

        // Point 0: bilinear H,D at fixed W, exchange, W-blend.
        float4 e0 = f4_fma2(s0FF, a0.w1h, s0FC, a0.w0h);
        float4 e1 = f4_fma2(s0CF, a0.w1h, s0CC, a0.w0h);
        float4 c0 = f4_fma2(e0, a0.w1d, e1, a0.w0d);

        float4 o0;
        o0.x = __shfl_xor_sync(0xffffffffu, c0.x, 1);
        o0.y = __shfl_xor_sync(0xffffffffu, c0.y, 1);
        o0.z = __shfl_xor_sync(0xffffffffu, c0.z, 1);
        o0.w = __shfl_xor_sync(0xffffffffu, c0.w, 1);

        // Point 1.
        float4 f0 = f4_fma2(s1FF, a1.w1h, s1FC, a1.w0h);
        float4 f1 = f4_fma2(s1CF, a1.w1h, s1CC, a1.w0h);
        float4 c1 = f4_fma2(f0, a1.w1d, f1, a1.w0d);

        float4 o1;
        o1.x = __shfl_xor_sync(0xffffffffu, c1.x, 1);
        o1.y = __shfl_xor_sync(0xffffffffu, c1.y, 1);
        o1.z = __shfl_xor_sync(0xffffffffu, c1.z, 1);
        o1.w = __shfl_xor_sync(0xffffffffu, c1.w, 1);

        if (s == 0) {
            stg_out(out + p0, f4_fma2(c0, a0.w1w, o0, a0.w0w));
            stg_out(out + p1, f4_fma2(c1, a1.w1w, o1, a1.w0w));
        }
    }
}

extern "C" void kernel_launch(void* const* d_in, const int* in_sizes, int n_in,
                              void* d_out, int out_size) {
    const float4* vol    = (const float4*)d_in[0];   // inputs [B,D,H,W,4] fp32
    const float*  coords = (const float*)d_in[1];    // sample_coords [B,OD,OH,OW,3]
    float4*       out    = (float4*)d_out;

    resampler_kernel<<<PERSIST_CTAS, CTA_THREADS>>>(vol, coords, out);
}

// round 17
// speedup vs baseline: 1.4062x; 1.4062x over previous
#include <cuda_runtime.h>

// ResamplerLayer: trilinear resample of [B,D,H,W,C=4] fp32 volume at
// [B,OD,OH,OW,3] continuous coords (ZERO boundary: weights from CLAMPED
// corner indices). Output [B,OD,OH,OW,4] fp32.
//
// FINAL configuration (best measured: 39.39us, reproduced twice).
// R4:  2 lanes per point (lane bit = floor-W / ceil-W) -> adjacent 16B pair
//      coalesces into one L1tex wavefront per gather instruction
//      (~4.5 lines/point instead of 8).
// R6:  2 points per thread (batch 0 + batch 1, same spatial offset) -> 8
//      independent gathers in flight per lane (MLP=8).
// R8:  L2 eviction policies: volume=evict_last (pin 67MB volume in 126MB
//      L2 across graph replays), coords=evict_first, stores=st.global.cs.
// R9:  __launch_bounds__(256,7) -> 32 regs.
// Probes that confirmed convergence at the L1tex random-gather wavefront
// floor: 8 CTAs/SM (neutral), .cg L1-bypass (worse), warp-coop coord loads
// (neutral), persistent grid-stride (much worse: serialized per-iteration
// gather latency). ~144 gather wavefronts/warp @ ~1 wf/cyc/SM == ~39us.

#define Bk   2
#define Dk   128
#define Hk   128
#define Wk   128
#define ODk  96
#define OHk  96
#define OWk  96

#define NPTS (Bk * ODk * OHk * OWk)          // 1,769,472
#define PTS_PER_BATCH (ODk * OHk * OWk)      // 884,736 == NPTS/2
#define VOLSZ (Dk * Hk * Wk)

__device__ __forceinline__ unsigned long long pol_evict_last() {
    unsigned long long p;
    asm("createpolicy.fractional.L2::evict_last.b64 %0, 1.0;" : "=l"(p));
    return p;
}

__device__ __forceinline__ unsigned long long pol_evict_first() {
    unsigned long long p;
    asm("createpolicy.fractional.L2::evict_first.b64 %0, 1.0;" : "=l"(p));
    return p;
}

// Volume gather: non-coherent load, pinned in L2 (evict_last policy).
__device__ __forceinline__ float4 ldg_vol(const float4* p, unsigned long long pol) {
    float4 v;
    asm volatile("ld.global.nc.L2::cache_hint.v4.f32 {%0,%1,%2,%3}, [%4], %5;"
                 : "=f"(v.x), "=f"(v.y), "=f"(v.z), "=f"(v.w)
                 : "l"(p), "l"(pol));
    return v;
}

// Coord load: streaming (evict_first policy).
__device__ __forceinline__ float ldg_coord(const float* p, unsigned long long pol) {
    float v;
    asm volatile("ld.global.nc.L2::cache_hint.f32 %0, [%1], %2;"
                 : "=f"(v) : "l"(p), "l"(pol));
    return v;
}

// Output store: cache-streaming.
__device__ __forceinline__ void stg_out(float4* p, float4 v) {
    asm volatile("st.global.cs.v4.f32 [%0], {%1,%2,%3,%4};"
                 :: "l"(p), "f"(v.x), "f"(v.y), "f"(v.z), "f"(v.w) : "memory");
}

__device__ __forceinline__ float4 f4_fma2(float4 a, float wa, float4 b, float wb) {
    float4 r;
    r.x = fmaf(a.x, wa, b.x * wb);
    r.y = fmaf(a.y, wa, b.y * wb);
    r.z = fmaf(a.z, wa, b.z * wb);
    r.w = fmaf(a.w, wa, b.w * wb);
    return r;
}

struct PtAddr {
    const float4* q;   // volume base + batch + this lane's W
    int rFF, rCF, rFC, rCC;
    float w0d, w1d, w0h, w1h, w0w, w1w;
};

__device__ __forceinline__ PtAddr make_addr(const float4* __restrict__ vol,
                                            const float* __restrict__ coords,
                                            int p, int batch_base, int s,
                                            unsigned long long polF) {
    const float* cp = coords + (size_t)p * 3;
    float cd = ldg_coord(cp + 0, polF);
    float ch = ldg_coord(cp + 1, polF);
    float cw = ldg_coord(cp + 2, polF);

    int fd0 = (int)floorf(cd);
    int fh0 = (int)floorf(ch);
    int fw0 = (int)floorf(cw);

    int fd  = min(max(fd0,     0), Dk - 1);
    int fh  = min(max(fh0,     0), Hk - 1);
    int fw  = min(max(fw0,     0), Wk - 1);
    int cdI = min(max(fd0 + 1, 0), Dk - 1);
    int chI = min(max(fh0 + 1, 0), Hk - 1);
    int cwI = min(max(fw0 + 1, 0), Wk - 1);

    PtAddr a;
    a.w0d = cd - (float)fd;    a.w1d = (float)cdI - cd;
    a.w0h = ch - (float)fh;    a.w1h = (float)chI - ch;
    a.w0w = cw - (float)fw;    a.w1w = (float)cwI - cw;

    int wsel = s ? cwI : fw;
    a.q = vol + batch_base + wsel;
    a.rFF = (fd  * Hk + fh ) * Wk;
    a.rCF = (cdI * Hk + fh ) * Wk;
    a.rFC = (fd  * Hk + chI) * Wk;
    a.rCC = (cdI * Hk + chI) * Wk;
    return a;
}

__global__ __launch_bounds__(256, 7)
void resampler_kernel(const float4* __restrict__ vol,     // [B,D,H,W] of float4
                      const float*  __restrict__ coords,  // [NPTS,3]
                      float4*       __restrict__ out)     // [NPTS] of float4
{
    unsigned long long polL = pol_evict_last();
    unsigned long long polF = pol_evict_first();

    int t = blockIdx.x * blockDim.x + threadIdx.x;        // exact-fit grid
    int q = t >> 1;                                       // pair index in [0, NPTS/2)
    int s = t & 1;                                        // 0 = floor-W, 1 = ceil-W

    int p0 = q;                    // batch 0
    int p1 = q + PTS_PER_BATCH;    // batch 1 (same spatial offset)

    PtAddr a0 = make_addr(vol, coords, p0, 0,     s, polF);
    PtAddr a1 = make_addr(vol, coords, p1, VOLSZ, s, polF);

    // 8 gathers back-to-back: MLP=8 per lane; lane pairs share 128B lines.
    float4 s0FF = ldg_vol(a0.q + a0.rFF, polL);
    float4 s0CF = ldg_vol(a0.q + a0.rCF, polL);
    float4 s0FC = ldg_vol(a0.q + a0.rFC, polL);
    float4 s0CC = ldg_vol(a0.q + a0.rCC, polL);
    float4 s1FF = ldg_vol(a1.q + a1.rFF, polL);
    float4 s1CF = ldg_vol(a1.q + a1.rCF, polL);
    float4 s1FC = ldg_vol(a1.q + a1.rFC, polL);
    float4 s1CC = ldg_vol(a1.q + a1.rCC, polL);

    // Point 0: bilinear H,D at fixed W, exchange, W-blend.
    float4 e0 = f4_fma2(s0FF, a0.w1h, s0FC, a0.w0h);
    float4 e1 = f4_fma2(s0CF, a0.w1h, s0CC, a0.w0h);
    float4 c0 = f4_fma2(e0, a0.w1d, e1, a0.w0d);

    float4 o0;
    o0.x = __shfl_xor_sync(0xffffffffu, c0.x, 1);
    o0.y = __shfl_xor_sync(0xffffffffu, c0.y, 1);
    o0.z = __shfl_xor_sync(0xffffffffu, c0.z, 1);
    o0.w = __shfl_xor_sync(0xffffffffu, c0.w, 1);

    // Point 1.
    float4 f0 = f4_fma2(s1FF, a1.w1h, s1FC, a1.w0h);
    float4 f1 = f4_fma2(s1CF, a1.w1h, s1CC, a1.w0h);
    float4 c1 = f4_fma2(f0, a1.w1d, f1, a1.w0d);

    float4 o1;
    o1.x = __shfl_xor_sync(0xffffffffu, c1.x, 1);
    o1.y = __shfl_xor_sync(0xffffffffu, c1.y, 1);
    o1.z = __shfl_xor_sync(0xffffffffu, c1.z, 1);
    o1.w = __shfl_xor_sync(0xffffffffu, c1.w, 1);

    if (s == 0) {
        stg_out(out + p0, f4_fma2(c0, a0.w1w, o0, a0.w0w));
        stg_out(out + p1, f4_fma2(c1, a1.w1w, o1, a1.w0w));
    }
}

extern "C" void kernel_launch(void* const* d_in, const int* in_sizes, int n_in,
                              void* d_out, int out_size) {
    const float4* vol    = (const float4*)d_in[0];   // inputs [B,D,H,W,4] fp32
    const float*  coords = (const float*)d_in[1];    // sample_coords [B,OD,OH,OW,3]
    float4*       out    = (float4*)d_out;

    const int threads = 256;
    const int blocks  = NPTS / threads;              // NPTS threads total, exact fit
    resampler_kernel<<<blocks, threads>>>(vol, coords, out);
}